// round 7
// baseline (speedup 1.0000x reference)
#include <cuda_runtime.h>

#define NB     4096
#define MAXK   128
#define MAXSID 128
#define NBLK   608
#define NTHR   512

// Bucket map — MUST be the identical expression for data and breakpoints
// (monotone in x), so the integer bucket logic in the prologue is exact.
__device__ __forceinline__ int bucket_of(float x, float scale, float offs) {
    unsigned b = __float2uint_rz(fmaf(x, scale, offs));   // negatives saturate to 0
    return (int)min(b, (unsigned)(NB - 1));
}

// Branchless flagged-bucket resolve. Safe for inactive lanes (clamped sid).
// Returns UNCLAMPED value; >=3-split sentinel records propagate NaN.
__device__ __forceinline__ float side_raw(bool on, float x, float tag, float old,
                                          const float4* __restrict__ s_side) {
    int sid = __float_as_int(tag);
    sid = min(max(sid, 0), MAXSID - 1);
    float4 A = s_side[2 * sid];
    float4 B = s_side[2 * sid + 1];
    int s = (x >= A.x) + (x >= A.y);            // INF/NaN compare false
    float aa = (s == 0) ? A.z : ((s == 1) ? B.x : B.z);
    float bb = (s == 0) ? A.w : ((s == 1) ? B.y : B.w);
    float y  = fmaf(bb, x, aa);                 // NaN if >=3-split record
    return on ? y : old;
}

// Exact searchsorted-'right' fallback; essentially never executed.
__device__ __noinline__ float search_eval(float x,
                                          const float* __restrict__ s_sx,
                                          const float* __restrict__ s_a,
                                          const float* __restrict__ s_b,
                                          int K) {
    int lo = 0, hi = K;
    while (lo < hi) {
        int mid = (lo + hi) >> 1;
        if (s_sx[mid] <= x) lo = mid + 1; else hi = mid;
    }
    int idx = min(max(lo, 1), K) - 1;
    return fmaf(s_b[idx], x, s_a[idx]);
}

__global__ void __launch_bounds__(NTHR, 4)
pwl_all(const float* __restrict__ x,
        const float* __restrict__ xp,
        const float* __restrict__ slopes,
        const float* __restrict__ biases,
        float* __restrict__ out, int n, int K) {
    __shared__ float2 s_lut[NB];                // {a,b} | {bitcast(sid), NaN}
    __shared__ float4 s_side[2 * MAXSID];       // {t1,t2,a0,b0},{a1,b1,a2,b2}
    __shared__ float  s_xp[MAXK], s_sx[MAXK], s_a[MAXK], s_b[MAXK];
    __shared__ int    s_bb[MAXK], s_sidv[MAXK];
    __shared__ float  sh_scale, sh_offs;

    const int t = threadIdx.x;

    // ---------------- Prologue: per-block table build (~1.5us) ----------------
    if (t < K) s_xp[t] = xp[t];
    __syncthreads();

    if (t < K) {                                 // stable rank sort, O(K^2)
        float v = s_xp[t];
        int r = 0;
        for (int j = 0; j < K; j++) {
            float w = s_xp[j];
            r += (w < v) || (w == v && j < t);
        }
        s_sx[r] = v;
    }
    __syncthreads();

    if (t == 0) {                                // betas -> affine y = a + b*x
        float beta = biases[0];
        for (int i = 0; i < K; i++) {
            float sl = slopes[i];
            s_a[i] = fmaf(-s_sx[i], sl, beta);
            s_b[i] = sl;
            if (i + 1 < K) beta = fmaf(s_sx[i + 1] - s_sx[i], sl, beta);
        }
        float range = s_sx[K - 1] - s_sx[0];
        sh_scale = (range > 0.0f) ? (float)NB / range : 0.0f;
        sh_offs  = -s_sx[0] * sh_scale;
    }
    __syncthreads();
    const float scale = sh_scale, offs = sh_offs;

    if (t < K) s_bb[t] = bucket_of(s_sx[t], scale, offs);   // monotone
    __syncthreads();

    if (t == 0) {                                // distinct-flagged rank per j
        int sid = 0;
        for (int j = 1; j < K; j++) {
            if (j == 1 || s_bb[j] != s_bb[j - 1]) sid++;
            s_sidv[j] = sid - 1;
        }
    }
    __syncthreads();

    const float QNAN = __int_as_float(0x7FC00000);
    const float INF  = __int_as_float(0x7F800000);

    for (int bkt = t; bkt < NB; bkt += NTHR) {
        // pl = #{j: bb[j] < bkt}, c = #{j: bb[j] == bkt} via binary search
        int lo = 0, hi = K;
        while (lo < hi) { int m = (lo + hi) >> 1; if (s_bb[m] < bkt) lo = m + 1; else hi = m; }
        int pl = lo;
        hi = K;
        while (lo < hi) { int m = (lo + hi) >> 1; if (s_bb[m] <= bkt) lo = m + 1; else hi = m; }
        int c = lo - pl;
        int idx0 = min(max(pl, 1), K) - 1;

        // effective (post-clip, equal-threshold-merged) transitions in bucket
        int   cur = idx0, eff = 0, g0 = idx0, g1 = idx0, g2 = idx0;
        float t1 = INF, t2 = INF, lastthr = 0.0f;
        for (int tt = 1; tt <= c; tt++) {
            int   ni  = min(max(pl + tt, 1), K) - 1;
            float thr = s_sx[pl + tt - 1];
            if (ni == cur) continue;
            if (eff >= 1 && thr == lastthr) {
                if (eff == 1) g1 = ni; else if (eff == 2) g2 = ni;
            } else {
                eff++;
                lastthr = thr;
                if (eff == 1)      { t1 = thr; g1 = ni; }
                else if (eff == 2) { t2 = thr; g2 = ni; }
            }
            cur = ni;
        }

        if (eff == 0) {
            s_lut[bkt] = make_float2(s_a[idx0], s_b[idx0]);
        } else {
            int jf  = max(pl, 1);                       // first j>=1 in bucket
            int sid = min(s_sidv[jf], MAXSID - 1);
            s_lut[bkt] = make_float2(__int_as_float(sid), QNAN);
            if (eff <= 2) {
                if (eff == 1) { t2 = INF; g2 = g1; }
                s_side[2 * sid]     = make_float4(t1, t2, s_a[g0], s_b[g0]);
                s_side[2 * sid + 1] = make_float4(s_a[g1], s_b[g1], s_a[g2], s_b[g2]);
            } else {                                    // >=3 splits: NaN record
                s_side[2 * sid]     = make_float4(QNAN, QNAN, QNAN, QNAN);
                s_side[2 * sid + 1] = make_float4(QNAN, QNAN, QNAN, QNAN);
            }
        }
    }
    __syncthreads();

    // ---------------- Main loop ----------------
    const int n4 = n >> 2;
    const float4* __restrict__ x4 = (const float4*)x;
    float4* __restrict__ o4 = (float4*)out;
    const int stride = gridDim.x * NTHR;

    #pragma unroll 2
    for (int i = blockIdx.x * NTHR + threadIdx.x; i < n4; i += stride) {
        float4 v = x4[i];
        float2 e0 = s_lut[bucket_of(v.x, scale, offs)];
        float2 e1 = s_lut[bucket_of(v.y, scale, offs)];
        float2 e2 = s_lut[bucket_of(v.z, scale, offs)];
        float2 e3 = s_lut[bucket_of(v.w, scale, offs)];

        float u0 = fmaf(e0.y, v.x, e0.x);
        float u1 = fmaf(e1.y, v.y, e1.x);
        float u2 = fmaf(e2.y, v.z, e2.x);
        float u3 = fmaf(e3.y, v.w, e3.x);

        bool f0 = (e0.y != e0.y), f1 = (e1.y != e1.y);
        bool f2 = (e2.y != e2.y), f3 = (e3.y != e3.y);
        if (f0 | f1 | f2 | f3) {                       // single hot branch
            u0 = side_raw(f0, v.x, e0.x, u0, s_side);
            u1 = side_raw(f1, v.y, e1.x, u1, s_side);
            u2 = side_raw(f2, v.z, e2.x, u2, s_side);
            u3 = side_raw(f3, v.w, e3.x, u3, s_side);
            if ((u0 != u0) | (u1 != u1) | (u2 != u2) | (u3 != u3)) {  // cold
                if (u0 != u0) u0 = search_eval(v.x, s_sx, s_a, s_b, K);
                if (u1 != u1) u1 = search_eval(v.y, s_sx, s_a, s_b, K);
                if (u2 != u2) u2 = search_eval(v.z, s_sx, s_a, s_b, K);
                if (u3 != u3) u3 = search_eval(v.w, s_sx, s_a, s_b, K);
            }
        }

        float4 r;
        r.x = fminf(fmaxf(u0, 0.0f), 1.0f);
        r.y = fminf(fmaxf(u1, 0.0f), 1.0f);
        r.z = fminf(fmaxf(u2, 0.0f), 1.0f);
        r.w = fminf(fmaxf(u3, 0.0f), 1.0f);
        o4[i] = r;
    }

    // Scalar tail
    int rem = n & 3;
    if (blockIdx.x == 0 && (int)threadIdx.x < rem) {
        int i = (n4 << 2) + threadIdx.x;
        float xv = x[i];
        float2 e = s_lut[bucket_of(xv, scale, offs)];
        float u = fmaf(e.y, xv, e.x);
        if (e.y != e.y) {
            u = side_raw(true, xv, e.x, u, s_side);
            if (u != u) u = search_eval(xv, s_sx, s_a, s_b, K);
        }
        out[i] = fminf(fmaxf(u, 0.0f), 1.0f);
    }
}

// ---------------------------------------------------------------------------
extern "C" void kernel_launch(void* const* d_in, const int* in_sizes, int n_in,
                              void* d_out, int out_size) {
    const float* x      = (const float*)d_in[0];
    const float* xp     = (const float*)d_in[1];
    const float* slopes = (const float*)d_in[2];
    const float* biases = (const float*)d_in[3];
    int K = in_sizes[1];
    if (K > MAXK) K = MAXK;

    pwl_all<<<NBLK, NTHR>>>(x, xp, slopes, biases, (float*)d_out, out_size, K);
}

// round 9
// speedup vs baseline: 2.0590x; 2.0590x over previous
#include <cuda_runtime.h>

#define NB     4096
#define MAXK   128
#define MAXSID 128
#define NBLK   608
#define NTHR   512
#define PREBLK 8
#define PRETHR 512

// Precomputed tables
__device__ float2 g_lutAB[NB];      // {a,b} clean | {bitcast(sid), NaN} flagged
__device__ float4 g_side[MAXSID];   // {t, a_lo, b_lo, b_hi} | all-NaN => >=2 splits
__device__ float  g_sx[MAXK];
__device__ float  g_a[MAXK];
__device__ float  g_b[MAXK];
__device__ float  g_scale;
__device__ float  g_offs;

// Bucket map — IDENTICAL expression for data and breakpoints (monotone in x),
// so the integer bucket logic in the precompute is exact.
__device__ __forceinline__ int bucket_of(float x, float scale, float offs) {
    unsigned b = __float2uint_rz(fmaf(x, scale, offs));   // negatives -> 0
    return (int)min(b, (unsigned)(NB - 1));
}

// ---------------------------------------------------------------------------
// Precompute: 8 blocks x 512 threads, one bucket per thread. Fully parallel:
// rank sort, Hillis-Steele scans for betas / sid ranks, binary-search fill.
// ---------------------------------------------------------------------------
__global__ void pwl_pre(const float* __restrict__ xp,
                        const float* __restrict__ slopes,
                        const float* __restrict__ biases,
                        int K) {
    __shared__ float s_xp[MAXK], s_sl[MAXK], s_sx[MAXK], s_a[MAXK], s_b[MAXK];
    __shared__ float s_scan[MAXK];
    __shared__ int   s_bb[MAXK], s_iscan[MAXK];
    __shared__ float sh_scale, sh_offs, sh_bias;

    const int t = threadIdx.x;

    if (t < K) { s_xp[t] = xp[t]; s_sl[t] = slopes[t]; }
    if (t == 0) sh_bias = biases[0];
    __syncthreads();

    // Stable rank sort, O(K^2) parallel
    if (t < K) {
        float v = s_xp[t];
        int r = 0;
        for (int j = 0; j < K; j++) {
            float w = s_xp[j];
            r += (w < v) || (w == v && j < t);
        }
        s_sx[r] = v;
    }
    __syncthreads();

    // d[i] = (sx[i+1]-sx[i]) * slopes[i]  (slopes in ORIGINAL order, per ref)
    if (t < MAXK) {
        float dv = 0.0f;
        if (t < K - 1) dv = (s_sx[t + 1] - s_sx[t]) * s_sl[t];
        s_scan[t] = dv;
    }
    __syncthreads();
    // Inclusive Hillis-Steele scan over MAXK slots
    for (int off = 1; off < MAXK; off <<= 1) {
        float add = 0.0f;
        if (t < MAXK && t >= off) add = s_scan[t - off];
        __syncthreads();
        if (t < MAXK) s_scan[t] += add;
        __syncthreads();
    }
    // beta[i] = bias + cum[i-1];  a[i] = beta[i] - sx[i]*b[i];  b[i] = slopes[i]
    if (t < K) {
        float beta = sh_bias + (t > 0 ? s_scan[t - 1] : 0.0f);
        s_b[t] = s_sl[t];
        s_a[t] = fmaf(-s_sx[t], s_sl[t], beta);
    }
    if (t == 0) {
        float range = s_sx[K - 1] - s_sx[0];
        sh_scale = (range > 0.0f) ? (float)NB / range : 0.0f;
        sh_offs  = -s_sx[0] * sh_scale;
    }
    __syncthreads();
    const float scale = sh_scale, offs = sh_offs;

    if (t < K) s_bb[t] = bucket_of(s_sx[t], scale, offs);   // monotone
    __syncthreads();

    // sid rank: flag[j]=1 if j>=1 starts a new distinct flagged bucket
    if (t < MAXK) {
        int f = 0;
        if (t >= 1 && t < K) f = (t == 1) || (s_bb[t] != s_bb[t - 1]);
        s_iscan[t] = f;
    }
    __syncthreads();
    for (int off = 1; off < MAXK; off <<= 1) {
        int add = 0;
        if (t < MAXK && t >= off) add = s_iscan[t - off];
        __syncthreads();
        if (t < MAXK) s_iscan[t] += add;
        __syncthreads();
    }
    // sid of the distinct flagged bucket containing breakpoint j = s_iscan[j]-1

    const float QNAN = __int_as_float(0x7FC00000);
    const float INF  = __int_as_float(0x7F800000);
    const int   bkt  = blockIdx.x * PRETHR + t;   // 8*512 = 4096 buckets

    // pl = #{j: bb[j] < bkt}, then count in-bucket, via binary search
    int lo = 0, hi = K;
    while (lo < hi) { int m = (lo + hi) >> 1; if (s_bb[m] < bkt) lo = m + 1; else hi = m; }
    const int pl = lo;
    hi = K;
    while (lo < hi) { int m = (lo + hi) >> 1; if (s_bb[m] <= bkt) lo = m + 1; else hi = m; }
    const int c = lo - pl;
    const int idx0 = min(max(pl, 1), K) - 1;

    // Effective (post-clip, equal-threshold-merged) transitions in bucket
    int   cur = idx0, eff = 0, g0 = idx0, g1 = idx0;
    float t1 = INF, lastthr = 0.0f;
    for (int tt = 1; tt <= c; tt++) {
        int   ni  = min(max(pl + tt, 1), K) - 1;
        float thr = s_sx[pl + tt - 1];
        if (ni == cur) continue;
        if (eff >= 1 && thr == lastthr) {
            if (eff == 1) g1 = ni;
        } else {
            eff++;
            lastthr = thr;
            if (eff == 1) { t1 = thr; g1 = ni; }
        }
        cur = ni;
    }

    if (eff == 0) {
        g_lutAB[bkt] = make_float2(s_a[idx0], s_b[idx0]);
    } else {
        int jf  = max(pl, 1);                       // first j>=1 in this bucket
        int sid = min(max(s_iscan[jf] - 1, 0), MAXSID - 1);
        g_lutAB[bkt] = make_float2(__int_as_float(sid), QNAN);
        if (eff == 1) {
            // one LDS.128 record; a_hi reconstructed from continuity
            g_side[sid] = make_float4(t1, s_a[g0], s_b[g0], s_b[g1]);
        } else {
            g_side[sid] = make_float4(QNAN, QNAN, QNAN, QNAN);  // cold path
        }
    }

    if (blockIdx.x == 0 && t < K) {
        g_sx[t] = s_sx[t];
        g_a[t]  = s_a[t];
        g_b[t]  = s_b[t];
        if (t == 0) { g_scale = scale; g_offs = offs; }
    }
}

// ---------------------------------------------------------------------------
// Main kernel
// ---------------------------------------------------------------------------

// Flagged resolve: ONE LDS.128 + selects. Safe for inactive lanes (clamped
// sid). Returns unclamped y; all-NaN records propagate NaN -> cold search.
__device__ __forceinline__ float side_raw(bool on, float x, float tag, float old,
                                          const float4* __restrict__ s_side) {
    int sid = __float_as_int(tag);
    sid = min(max(sid, 0), MAXSID - 1);
    float4 A = s_side[sid];                       // {t, a_lo, b_lo, b_hi}
    bool  ge = (x >= A.x);                        // false for NaN record
    float bb = ge ? A.w : A.z;
    float aa = ge ? fmaf(A.x, A.z - A.w, A.y) : A.y;   // continuity: a_hi
    float y  = fmaf(bb, x, aa);                   // NaN record -> NaN ✓
    return on ? y : old;
}

// Exact searchsorted-'right' fallback; cold (multi-split buckets only).
__device__ __noinline__ float search_eval(float x,
                                          const float* __restrict__ s_sx,
                                          const float* __restrict__ s_a,
                                          const float* __restrict__ s_b,
                                          int K) {
    int lo = 0, hi = K;
    while (lo < hi) {
        int mid = (lo + hi) >> 1;
        if (s_sx[mid] <= x) lo = mid + 1; else hi = mid;
    }
    int idx = min(max(lo, 1), K) - 1;
    return fmaf(s_b[idx], x, s_a[idx]);
}

__global__ void __launch_bounds__(NTHR, 4)
pwl_main(const float* __restrict__ x, float* __restrict__ out, int n, int K) {
    __shared__ float2 s_lut[NB];
    __shared__ float4 s_side[MAXSID];
    __shared__ float  s_sx[MAXK], s_a[MAXK], s_b[MAXK];

    for (int i = threadIdx.x; i < NB; i += NTHR) s_lut[i] = g_lutAB[i];
    if (threadIdx.x < MAXSID) s_side[threadIdx.x] = g_side[threadIdx.x];
    if (threadIdx.x < MAXK) {
        int i = threadIdx.x;
        s_sx[i] = g_sx[i];
        s_a[i]  = g_a[i];
        s_b[i]  = g_b[i];
    }
    __syncthreads();

    const float scale = g_scale, offs = g_offs;
    const int n4 = n >> 2;
    const float4* __restrict__ x4 = (const float4*)x;
    float4* __restrict__ o4 = (float4*)out;
    const int stride = gridDim.x * NTHR;

    #pragma unroll 2
    for (int i = blockIdx.x * NTHR + threadIdx.x; i < n4; i += stride) {
        float4 v = x4[i];
        float2 e0 = s_lut[bucket_of(v.x, scale, offs)];
        float2 e1 = s_lut[bucket_of(v.y, scale, offs)];
        float2 e2 = s_lut[bucket_of(v.z, scale, offs)];
        float2 e3 = s_lut[bucket_of(v.w, scale, offs)];

        float u0 = fmaf(e0.y, v.x, e0.x);
        float u1 = fmaf(e1.y, v.y, e1.x);
        float u2 = fmaf(e2.y, v.z, e2.x);
        float u3 = fmaf(e3.y, v.w, e3.x);

        bool f0 = (e0.y != e0.y), f1 = (e1.y != e1.y);
        bool f2 = (e2.y != e2.y), f3 = (e3.y != e3.y);
        if (f0 | f1 | f2 | f3) {                     // hot branch, slim body
            u0 = side_raw(f0, v.x, e0.x, u0, s_side);
            u1 = side_raw(f1, v.y, e1.x, u1, s_side);
            u2 = side_raw(f2, v.z, e2.x, u2, s_side);
            u3 = side_raw(f3, v.w, e3.x, u3, s_side);
            if ((u0 != u0) | (u1 != u1) | (u2 != u2) | (u3 != u3)) {  // cold
                if (u0 != u0) u0 = search_eval(v.x, s_sx, s_a, s_b, K);
                if (u1 != u1) u1 = search_eval(v.y, s_sx, s_a, s_b, K);
                if (u2 != u2) u2 = search_eval(v.z, s_sx, s_a, s_b, K);
                if (u3 != u3) u3 = search_eval(v.w, s_sx, s_a, s_b, K);
            }
        }

        float4 r;
        r.x = fminf(fmaxf(u0, 0.0f), 1.0f);
        r.y = fminf(fmaxf(u1, 0.0f), 1.0f);
        r.z = fminf(fmaxf(u2, 0.0f), 1.0f);
        r.w = fminf(fmaxf(u3, 0.0f), 1.0f);
        o4[i] = r;
    }

    // Scalar tail
    int rem = n & 3;
    if (blockIdx.x == 0 && (int)threadIdx.x < rem) {
        int i = (n4 << 2) + threadIdx.x;
        float xv = x[i];
        float2 e = s_lut[bucket_of(xv, scale, offs)];
        float u = fmaf(e.y, xv, e.x);
        if (e.y != e.y) {
            u = side_raw(true, xv, e.x, u, s_side);
            if (u != u) u = search_eval(xv, s_sx, s_a, s_b, K);
        }
        out[i] = fminf(fmaxf(u, 0.0f), 1.0f);
    }
}

// ---------------------------------------------------------------------------
extern "C" void kernel_launch(void* const* d_in, const int* in_sizes, int n_in,
                              void* d_out, int out_size) {
    const float* x      = (const float*)d_in[0];
    const float* xp     = (const float*)d_in[1];
    const float* slopes = (const float*)d_in[2];
    const float* biases = (const float*)d_in[3];
    int K = in_sizes[1];
    if (K > MAXK) K = MAXK;

    pwl_pre<<<PREBLK, PRETHR>>>(xp, slopes, biases, K);
    pwl_main<<<NBLK, NTHR>>>(x, (float*)d_out, out_size, K);
}

// round 10
// speedup vs baseline: 2.2577x; 1.0965x over previous
#include <cuda_runtime.h>
#include <cuda_fp16.h>

#define NB     8192
#define MAXK   128
#define MAXSID 128
#define NBLK   608
#define NTHR   512
#define PREBLK 8
#define PRETHR 1024   // NB/PREBLK buckets, one per thread

// Precomputed tables
__device__ unsigned g_lutU[NB];     // {fp16 b' | u16 cq}  or  {fp16 NaN | sid}
__device__ float4   g_side[MAXSID]; // {t, a_lo, b_lo, b_hi} | all-NaN => >=2 splits
__device__ float    g_sx[MAXK];
__device__ float    g_a[MAXK];
__device__ float    g_b[MAXK];
__device__ float    g_scale, g_offs, g_qbase, g_qstep;

// Bucket map — IDENTICAL expression for data and breakpoints (monotone in x).
__device__ __forceinline__ unsigned bucket_of(float x, float scale, float offs) {
    unsigned b = __float2uint_rz(fmaf(x, scale, offs));   // negatives -> 0
    return min(b, (unsigned)(NB - 1));
}

// ---------------------------------------------------------------------------
// Precompute: 8 blocks x 1024 threads, one bucket per thread. Every block
// redundantly derives sort/scan/quant-range (identical deterministic fp ops),
// then fills its NB/8 slice.
// ---------------------------------------------------------------------------
__global__ void pwl_pre(const float* __restrict__ xp,
                        const float* __restrict__ slopes,
                        const float* __restrict__ biases,
                        int K) {
    __shared__ float s_xp[MAXK], s_sl[MAXK], s_sx[MAXK], s_a[MAXK], s_b[MAXK];
    __shared__ float s_scan[MAXK];
    __shared__ float s_rmin[MAXK], s_rmax[MAXK];
    __shared__ int   s_bb[MAXK], s_iscan[MAXK];
    __shared__ float sh_scale, sh_offs, sh_bias, sh_qbase, sh_qstep;

    const int t = threadIdx.x;

    if (t < K) { s_xp[t] = xp[t]; s_sl[t] = slopes[t]; }
    if (t == 0) sh_bias = biases[0];
    __syncthreads();

    // Stable rank sort, O(K^2) parallel
    if (t < K) {
        float v = s_xp[t];
        int r = 0;
        for (int j = 0; j < K; j++) {
            float w = s_xp[j];
            r += (w < v) || (w == v && j < t);
        }
        s_sx[r] = v;
    }
    __syncthreads();

    // d[i] = (sx[i+1]-sx[i]) * slopes[i]
    if (t < MAXK) {
        float dv = 0.0f;
        if (t < K - 1) dv = (s_sx[t + 1] - s_sx[t]) * s_sl[t];
        s_scan[t] = dv;
    }
    __syncthreads();
    for (int off = 1; off < MAXK; off <<= 1) {      // inclusive Hillis-Steele
        float add = 0.0f;
        if (t < MAXK && t >= off) add = s_scan[t - off];
        __syncthreads();
        if (t < MAXK) s_scan[t] += add;
        __syncthreads();
    }
    // beta[i] = bias + cum[i-1];  a[i] = beta[i] - sx[i]*b[i]
    if (t < MAXK) {
        float beta = sh_bias + (t > 0 ? s_scan[t - 1] : 0.0f);
        if (t < K) {
            s_b[t] = s_sl[t];
            s_a[t] = fmaf(-s_sx[t], s_sl[t], beta);
        }
        // quantization range = [min,max] of betas (PWL extremes at breakpoints)
        s_rmin[t] = (t < K) ? beta :  3.4e38f;
        s_rmax[t] = (t < K) ? beta : -3.4e38f;
    }
    if (t == 0) {
        float range = s_sx[K - 1] - s_sx[0];
        sh_scale = (range > 0.0f) ? (float)NB / range : 0.0f;
        sh_offs  = -s_sx[0] * sh_scale;
    }
    __syncthreads();
    for (int off = MAXK / 2; off > 0; off >>= 1) {  // min/max tree reduce
        if (t < off) {
            s_rmin[t] = fminf(s_rmin[t], s_rmin[t + off]);
            s_rmax[t] = fmaxf(s_rmax[t], s_rmax[t + off]);
        }
        __syncthreads();
    }
    if (t == 0) {
        float qr = s_rmax[0] - s_rmin[0];
        sh_qbase = s_rmin[0];
        sh_qstep = (qr > 0.0f) ? qr / 65535.0f : 1.0f;
        if (blockIdx.x == 0) {
            g_scale = sh_scale; g_offs = sh_offs;
            g_qbase = sh_qbase; g_qstep = sh_qstep;
        }
    }
    __syncthreads();
    const float scale = sh_scale, offs = sh_offs;
    const float qbase = sh_qbase, qstep = sh_qstep;

    if (t < K) s_bb[t] = (int)bucket_of(s_sx[t], scale, offs);   // monotone
    __syncthreads();

    // sid rank: flag[j]=1 if j>=1 starts a new distinct flagged bucket
    if (t < MAXK) {
        int f = 0;
        if (t >= 1 && t < K) f = (t == 1) || (s_bb[t] != s_bb[t - 1]);
        s_iscan[t] = f;
    }
    __syncthreads();
    for (int off = 1; off < MAXK; off <<= 1) {
        int add = 0;
        if (t < MAXK && t >= off) add = s_iscan[t - off];
        __syncthreads();
        if (t < MAXK) s_iscan[t] += add;
        __syncthreads();
    }

    const float QNAN = __int_as_float(0x7FC00000);
    const float INF  = __int_as_float(0x7F800000);
    const int   bkt  = blockIdx.x * PRETHR + t;     // 8*1024 = 8192

    // pl = #{j: bb[j] < bkt}, c = #{j: bb[j] == bkt} via binary search
    int lo = 0, hi = K;
    while (lo < hi) { int m = (lo + hi) >> 1; if (s_bb[m] < bkt) lo = m + 1; else hi = m; }
    const int pl = lo;
    hi = K;
    while (lo < hi) { int m = (lo + hi) >> 1; if (s_bb[m] <= bkt) lo = m + 1; else hi = m; }
    const int c = lo - pl;
    const int idx0 = min(max(pl, 1), K) - 1;

    // Effective (post-clip, equal-threshold-merged) transitions in bucket
    int   cur = idx0, eff = 0, g0 = idx0, g1 = idx0;
    float t1 = INF, lastthr = 0.0f;
    for (int tt = 1; tt <= c; tt++) {
        int   ni  = min(max(pl + tt, 1), K) - 1;
        float thr = s_sx[pl + tt - 1];
        if (ni == cur) continue;
        if (eff >= 1 && thr == lastthr) {
            if (eff == 1) g1 = ni;
        } else {
            eff++;
            lastthr = thr;
            if (eff == 1) { t1 = thr; g1 = ni; }
        }
        cur = ni;
    }

    if (eff == 0) {
        // c_left = PWL at bucket left edge; b' = b/scale (grid units)
        float x_left = ((float)bkt - offs) / scale;       // scale==0 never read
        float cl = fmaf(s_b[idx0], x_left, s_a[idx0]);
        int cq = __float2int_rn((cl - qbase) / qstep);
        cq = min(max(cq, 0), 65535);
        unsigned short bh = __half_as_ushort(__float2half_rn(s_b[idx0] / scale));
        g_lutU[bkt] = ((unsigned)bh << 16) | (unsigned)cq;
    } else {
        int jf  = max(pl, 1);
        int sid = min(max(s_iscan[jf] - 1, 0), MAXSID - 1);
        g_lutU[bkt] = (0x7E00u << 16) | (unsigned)sid;    // fp16 NaN | sid
        if (eff == 1) {
            g_side[sid] = make_float4(t1, s_a[g0], s_b[g0], s_b[g1]);
        } else {
            g_side[sid] = make_float4(QNAN, QNAN, QNAN, QNAN);
        }
    }

    if (blockIdx.x == 0 && t < K) {
        g_sx[t] = s_sx[t];
        g_a[t]  = s_a[t];
        g_b[t]  = s_b[t];
    }
}

// ---------------------------------------------------------------------------
// Main kernel
// ---------------------------------------------------------------------------

// Flagged resolve: ONE LDS.128 + selects; exact fp32. Safe for inactive lanes.
__device__ __forceinline__ float side_raw(bool on, float x, unsigned e, float old,
                                          const float4* __restrict__ s_side) {
    int sid = (int)(e & 0xFFFFu);
    sid = min(sid, MAXSID - 1);
    float4 A = s_side[sid];                        // {t, a_lo, b_lo, b_hi}
    bool  ge = (x >= A.x);                         // false for NaN record
    float bb = ge ? A.w : A.z;
    float aa = ge ? fmaf(A.x, A.z - A.w, A.y) : A.y;
    float y  = fmaf(bb, x, aa);                    // NaN record -> NaN
    return on ? y : old;
}

__device__ __noinline__ float search_eval(float x,
                                          const float* __restrict__ s_sx,
                                          const float* __restrict__ s_a,
                                          const float* __restrict__ s_b,
                                          int K) {
    int lo = 0, hi = K;
    while (lo < hi) {
        int mid = (lo + hi) >> 1;
        if (s_sx[mid] <= x) lo = mid + 1; else hi = mid;
    }
    int idx = min(max(lo, 1), K) - 1;
    return fmaf(s_b[idx], x, s_a[idx]);
}

// Decode one element: 4-byte entry, single-phase LDS.32 gather.
__device__ __forceinline__ float pwl_dec(float x, float scale, float offs,
                                         float qbase, float qstep,
                                         const unsigned* __restrict__ s_lut,
                                         unsigned& e_out) {
    float gf = fmaf(x, scale, offs);
    unsigned bi = min(__float2uint_rz(gf), (unsigned)(NB - 1));
    unsigned e = s_lut[bi];
    e_out = e;
    float frac = gf - (float)bi;                   // exact (Sterbenz / extrapolation)
    float cc = fmaf((float)(e & 0xFFFFu), qstep, qbase);
    float bw = __half2float(__ushort_as_half((unsigned short)(e >> 16)));
    return fmaf(bw, frac, cc);                     // NaN if flagged
}

__global__ void __launch_bounds__(NTHR, 4)
pwl_main(const float* __restrict__ x, float* __restrict__ out, int n, int K) {
    __shared__ unsigned s_lut[NB];
    __shared__ float4   s_side[MAXSID];
    __shared__ float    s_sx[MAXK], s_a[MAXK], s_b[MAXK];

    {   // stage LUT with uint4 loads
        const uint4* src = (const uint4*)g_lutU;
        uint4* dst = (uint4*)s_lut;
        for (int i = threadIdx.x; i < NB / 4; i += NTHR) dst[i] = src[i];
        if (threadIdx.x < MAXSID) s_side[threadIdx.x] = g_side[threadIdx.x];
        if (threadIdx.x < MAXK) {
            int i = threadIdx.x;
            s_sx[i] = g_sx[i]; s_a[i] = g_a[i]; s_b[i] = g_b[i];
        }
    }
    __syncthreads();

    const float scale = g_scale, offs = g_offs;
    const float qbase = g_qbase, qstep = g_qstep;
    const int n4 = n >> 2;
    const float4* __restrict__ x4 = (const float4*)x;
    float4* __restrict__ o4 = (float4*)out;
    const int stride = gridDim.x * NTHR;

    #pragma unroll 2
    for (int i = blockIdx.x * NTHR + threadIdx.x; i < n4; i += stride) {
        float4 v = x4[i];
        unsigned e0, e1, e2, e3;
        float u0 = pwl_dec(v.x, scale, offs, qbase, qstep, s_lut, e0);
        float u1 = pwl_dec(v.y, scale, offs, qbase, qstep, s_lut, e1);
        float u2 = pwl_dec(v.z, scale, offs, qbase, qstep, s_lut, e2);
        float u3 = pwl_dec(v.w, scale, offs, qbase, qstep, s_lut, e3);

        bool f0 = (u0 != u0), f1 = (u1 != u1), f2 = (u2 != u2), f3 = (u3 != u3);
        if (f0 | f1 | f2 | f3) {                   // hot branch, slim body
            u0 = side_raw(f0, v.x, e0, u0, s_side);
            u1 = side_raw(f1, v.y, e1, u1, s_side);
            u2 = side_raw(f2, v.z, e2, u2, s_side);
            u3 = side_raw(f3, v.w, e3, u3, s_side);
            if ((u0 != u0) | (u1 != u1) | (u2 != u2) | (u3 != u3)) {  // cold
                if (u0 != u0) u0 = search_eval(v.x, s_sx, s_a, s_b, K);
                if (u1 != u1) u1 = search_eval(v.y, s_sx, s_a, s_b, K);
                if (u2 != u2) u2 = search_eval(v.z, s_sx, s_a, s_b, K);
                if (u3 != u3) u3 = search_eval(v.w, s_sx, s_a, s_b, K);
            }
        }

        float4 r;
        r.x = fminf(fmaxf(u0, 0.0f), 1.0f);
        r.y = fminf(fmaxf(u1, 0.0f), 1.0f);
        r.z = fminf(fmaxf(u2, 0.0f), 1.0f);
        r.w = fminf(fmaxf(u3, 0.0f), 1.0f);
        o4[i] = r;
    }

    // Scalar tail
    int rem = n & 3;
    if (blockIdx.x == 0 && (int)threadIdx.x < rem) {
        int i = (n4 << 2) + threadIdx.x;
        float xv = x[i];
        unsigned e;
        float u = pwl_dec(xv, scale, offs, qbase, qstep, s_lut, e);
        if (u != u) {
            u = side_raw(true, xv, e, u, s_side);
            if (u != u) u = search_eval(xv, s_sx, s_a, s_b, K);
        }
        out[i] = fminf(fmaxf(u, 0.0f), 1.0f);
    }
}

// ---------------------------------------------------------------------------
extern "C" void kernel_launch(void* const* d_in, const int* in_sizes, int n_in,
                              void* d_out, int out_size) {
    const float* x      = (const float*)d_in[0];
    const float* xp     = (const float*)d_in[1];
    const float* slopes = (const float*)d_in[2];
    const float* biases = (const float*)d_in[3];
    int K = in_sizes[1];
    if (K > MAXK) K = MAXK;

    pwl_pre<<<PREBLK, PRETHR>>>(xp, slopes, biases, K);
    pwl_main<<<NBLK, NTHR>>>(x, (float*)d_out, out_size, K);
}